// round 4
// baseline (speedup 1.0000x reference)
#include <cuda_runtime.h>

#define AA 8192
#define BB 8192
#define KK 10

// Scratch (no allocations allowed): per-row fold coefficients and block sums.
__device__ float d_cs[AA * 12];        // [a][12]: c0..c9, s, pad
__device__ float d_bsum[8 * 128];      // one partial per block (8 col-chunks x 128 row-chunks)

// ---------------- packed f32x2 helpers ----------------
__device__ __forceinline__ unsigned long long f2pk(float lo, float hi) {
    unsigned long long r;
    asm("mov.b64 %0, {%1, %2};" : "=l"(r) : "f"(lo), "f"(hi));
    return r;
}
__device__ __forceinline__ unsigned long long f2dup(float v) { return f2pk(v, v); }
__device__ __forceinline__ unsigned long long f2fma(unsigned long long a, unsigned long long b,
                                                    unsigned long long c) {
    unsigned long long d;
    asm("fma.rn.f32x2 %0, %1, %2, %3;" : "=l"(d) : "l"(a), "l"(b), "l"(c));
    return d;
}
__device__ __forceinline__ unsigned long long f2mul(unsigned long long a, unsigned long long b) {
    unsigned long long d;
    asm("mul.rn.f32x2 %0, %1, %2;" : "=l"(d) : "l"(a), "l"(b));
    return d;
}
__device__ __forceinline__ unsigned long long f2add(unsigned long long a, unsigned long long b) {
    unsigned long long d;
    asm("add.rn.f32x2 %0, %1, %2;" : "=l"(d) : "l"(a), "l"(b));
    return d;
}
__device__ __forceinline__ float f2sum(unsigned long long a) {
    float lo, hi;
    asm("mov.b64 {%0, %1}, %2;" : "=f"(lo), "=f"(hi) : "l"(a));
    return lo + hi;
}

// ---------------- kernel 1: precompute fold coefficients ----------------
// c[a][k] = (1 - 2*P_l[a,k]) / cp[k],  s[a] = sum_k P_l[a,k] / cp[k]
__global__ void prcut_prep(const float* __restrict__ Pl, const float* __restrict__ cp) {
    int a = blockIdx.x * blockDim.x + threadIdx.x;
    if (a >= AA) return;
    float inv[KK];
#pragma unroll
    for (int k = 0; k < KK; k++) inv[k] = 1.0f / __ldg(&cp[k]);
    float s = 0.0f;
#pragma unroll
    for (int k = 0; k < KK; k++) {
        float pl = __ldg(&Pl[a * KK + k]);
        d_cs[a * 12 + k] = (1.0f - 2.0f * pl) * inv[k];
        s = fmaf(pl, inv[k], s);
    }
    d_cs[a * 12 + 10] = s;
    d_cs[a * 12 + 11] = 0.0f;
}

// ---------------- kernel 2: main pass over W (one read, fully fused) ----------------
// Each lane owns 4 consecutive b-columns; P_r pairs live in registers.
// Per row: acc[k] = w0*pr[b0,k] + w1*pr[b1,k] + w2*pr[b2,k] + w3*pr[b3,k] (packed pairs),
//          fold into private total with c_{a,k}, s_a.  Linear => no per-row cross-lane reduce.
__global__ __launch_bounds__(256, 2)
void prcut_main(const float* __restrict__ W, const float* __restrict__ Pr) {
    const int col  = blockIdx.x * 1024 + threadIdx.x * 4;   // 8 col-chunks of 1024
    const int row0 = blockIdx.y * 64;                        // 128 row-chunks of 64

    // P_r register tile: pairs (P_r[b0,k],P_r[b1,k]) and (P_r[b2,k],P_r[b3,k])
    unsigned long long prp01[KK], prp23[KK];
#pragma unroll
    for (int k = 0; k < KK; k++) {
        float a0 = __ldg(&Pr[(col + 0) * KK + k]);
        float a1 = __ldg(&Pr[(col + 1) * KK + k]);
        float a2 = __ldg(&Pr[(col + 2) * KK + k]);
        float a3 = __ldg(&Pr[(col + 3) * KK + k]);
        prp01[k] = f2pk(a0, a1);
        prp23[k] = f2pk(a2, a3);
    }

    unsigned long long totA = 0ull, totB = 0ull;   // bit pattern 0 == (0.f, 0.f)
    const float4* wp  = reinterpret_cast<const float4*>(W + (size_t)row0 * BB + col);
    const float4* csP = reinterpret_cast<const float4*>(d_cs + row0 * 12);
    const size_t wstep = BB / 4;   // one row in float4 units

#pragma unroll 2
    for (int r = 0; r < 64; r++) {
        float4 w   = __ldg(wp);
        float4 cs0 = csP[0];
        float4 cs1 = csP[1];
        float4 cs2 = csP[2];
        wp  += wstep;
        csP += 3;

        unsigned long long p01 = f2pk(w.x, w.y);
        unsigned long long p23 = f2pk(w.z, w.w);
        unsigned long long acc;

        // rsum * s_a
        acc = f2add(p01, p23);
        totA = f2fma(acc, f2dup(cs2.z), totA);
        // k = 0..9, alternating accumulators to break the dependency chain
        acc = f2fma(p01, prp01[0], f2mul(p23, prp23[0])); totB = f2fma(acc, f2dup(cs0.x), totB);
        acc = f2fma(p01, prp01[1], f2mul(p23, prp23[1])); totA = f2fma(acc, f2dup(cs0.y), totA);
        acc = f2fma(p01, prp01[2], f2mul(p23, prp23[2])); totB = f2fma(acc, f2dup(cs0.z), totB);
        acc = f2fma(p01, prp01[3], f2mul(p23, prp23[3])); totA = f2fma(acc, f2dup(cs0.w), totA);
        acc = f2fma(p01, prp01[4], f2mul(p23, prp23[4])); totB = f2fma(acc, f2dup(cs1.x), totB);
        acc = f2fma(p01, prp01[5], f2mul(p23, prp23[5])); totA = f2fma(acc, f2dup(cs1.y), totA);
        acc = f2fma(p01, prp01[6], f2mul(p23, prp23[6])); totB = f2fma(acc, f2dup(cs1.z), totB);
        acc = f2fma(p01, prp01[7], f2mul(p23, prp23[7])); totA = f2fma(acc, f2dup(cs1.w), totA);
        acc = f2fma(p01, prp01[8], f2mul(p23, prp23[8])); totB = f2fma(acc, f2dup(cs2.x), totB);
        acc = f2fma(p01, prp01[9], f2mul(p23, prp23[9])); totA = f2fma(acc, f2dup(cs2.y), totA);
    }

    float t = f2sum(totA) + f2sum(totB);

    // warp reduce
#pragma unroll
    for (int off = 16; off > 0; off >>= 1)
        t += __shfl_xor_sync(0xFFFFFFFFu, t, off);

    __shared__ float sred[8];
    const int wid = threadIdx.x >> 5;
    const int lid = threadIdx.x & 31;
    if (lid == 0) sred[wid] = t;
    __syncthreads();
    if (threadIdx.x == 0) {
        float s = 0.0f;
#pragma unroll
        for (int i = 0; i < 8; i++) s += sred[i];
        d_bsum[blockIdx.y * 8 + blockIdx.x] = s;
    }
}

// ---------------- kernel 3: deterministic final reduction ----------------
__global__ void prcut_final(float* __restrict__ out) {
    __shared__ float s[1024];
    int t = threadIdx.x;
    s[t] = d_bsum[t];
    __syncthreads();
#pragma unroll
    for (int off = 512; off > 0; off >>= 1) {
        if (t < off) s[t] += s[t + off];
        __syncthreads();
    }
    if (t == 0) out[0] = s[0];
}

extern "C" void kernel_launch(void* const* d_in, const int* in_sizes, int n_in,
                              void* d_out, int out_size) {
    const float* W  = (const float*)d_in[0];
    const float* Pl = (const float*)d_in[1];
    const float* Pr = (const float*)d_in[2];
    const float* cp = (const float*)d_in[3];
    float* out = (float*)d_out;

    prcut_prep<<<AA / 256, 256>>>(Pl, cp);
    prcut_main<<<dim3(8, 128), 256>>>(W, Pr);
    prcut_final<<<1, 1024>>>(out);
}

// round 6
// speedup vs baseline: 1.1467x; 1.1467x over previous
#include <cuda_runtime.h>

#define AA 8192
#define BB 8192
#define KK 10
#define NBLK 296          // 2 CTAs/SM on 148 SMs (<=2/SM on 152) -> single wave
#define NTILE 2048        // 8 col-chunks x 256 row-tiles
#define ROWS_PER_TILE 32

// Scratch (no allocations allowed).
__device__ unsigned long long d_cs2[AA * 12];  // [a][12] f32x2 pairs: c0..c9 (dup), s (dup), pad
__device__ float d_bsum[NBLK];

// ---------------- packed f32x2 helpers ----------------
__device__ __forceinline__ unsigned long long f2pk(float lo, float hi) {
    unsigned long long r;
    asm("mov.b64 %0, {%1, %2};" : "=l"(r) : "f"(lo), "f"(hi));
    return r;
}
__device__ __forceinline__ unsigned long long f2fma(unsigned long long a, unsigned long long b,
                                                    unsigned long long c) {
    unsigned long long d;
    asm("fma.rn.f32x2 %0, %1, %2, %3;" : "=l"(d) : "l"(a), "l"(b), "l"(c));
    return d;
}
__device__ __forceinline__ unsigned long long f2mul(unsigned long long a, unsigned long long b) {
    unsigned long long d;
    asm("mul.rn.f32x2 %0, %1, %2;" : "=l"(d) : "l"(a), "l"(b));
    return d;
}
__device__ __forceinline__ unsigned long long f2add(unsigned long long a, unsigned long long b) {
    unsigned long long d;
    asm("add.rn.f32x2 %0, %1, %2;" : "=l"(d) : "l"(a), "l"(b));
    return d;
}
__device__ __forceinline__ float f2sum(unsigned long long a) {
    float lo, hi;
    asm("mov.b64 {%0, %1}, %2;" : "=f"(lo), "=f"(hi) : "l"(a));
    return lo + hi;
}

// ---------------- kernel 1: fold coefficients as pre-duplicated pairs ----------------
// c[a][k] = (1 - 2*P_l[a,k]) / cp[k] (dup),  s[a] = sum_k P_l[a,k] / cp[k] (dup)
__global__ void prcut_prep(const float* __restrict__ Pl, const float* __restrict__ cp) {
    __shared__ float sh[640];
    const int row0 = blockIdx.x * 64;
    float inv[KK];
#pragma unroll
    for (int k = 0; k < KK; k++) inv[k] = 1.0f / __ldg(&cp[k]);

    for (int idx = threadIdx.x; idx < 64 * KK; idx += 256) {
        int ar = idx / KK;
        int k  = idx % KK;
        float pl = __ldg(&Pl[(size_t)(row0 + ar) * KK + k]);
        float c = (1.0f - 2.0f * pl) * inv[k];
        d_cs2[(size_t)(row0 + ar) * 12 + k] = f2pk(c, c);
        sh[idx] = pl * inv[k];
    }
    __syncthreads();
    if (threadIdx.x < 64) {
        float s = 0.0f;
#pragma unroll
        for (int k = 0; k < KK; k++) s += sh[threadIdx.x * KK + k];
        d_cs2[(size_t)(row0 + threadIdx.x) * 12 + 10] = f2pk(s, s);
        d_cs2[(size_t)(row0 + threadIdx.x) * 12 + 11] = 0ull;
    }
}

// ---------------- per-row fold (fully inlined, constant indices) ----------------
__device__ __forceinline__ void row_accum(float4 w, int a,
                                          const unsigned long long* prp01,
                                          const unsigned long long* prp23,
                                          unsigned long long& totA,
                                          unsigned long long& totB) {
    const ulonglong2* cs = reinterpret_cast<const ulonglong2*>(d_cs2 + (size_t)a * 12);
    ulonglong2 c01 = __ldg(cs + 0);
    ulonglong2 c23 = __ldg(cs + 1);
    ulonglong2 c45 = __ldg(cs + 2);
    ulonglong2 c67 = __ldg(cs + 3);
    ulonglong2 c89 = __ldg(cs + 4);
    ulonglong2 cS  = __ldg(cs + 5);

    unsigned long long p01 = f2pk(w.x, w.y);
    unsigned long long p23 = f2pk(w.z, w.w);
    unsigned long long acc;

    acc = f2add(p01, p23);                                      totA = f2fma(acc, cS.x,  totA);
    acc = f2fma(p01, prp01[0], f2mul(p23, prp23[0]));           totB = f2fma(acc, c01.x, totB);
    acc = f2fma(p01, prp01[1], f2mul(p23, prp23[1]));           totA = f2fma(acc, c01.y, totA);
    acc = f2fma(p01, prp01[2], f2mul(p23, prp23[2]));           totB = f2fma(acc, c23.x, totB);
    acc = f2fma(p01, prp01[3], f2mul(p23, prp23[3]));           totA = f2fma(acc, c23.y, totA);
    acc = f2fma(p01, prp01[4], f2mul(p23, prp23[4]));           totB = f2fma(acc, c45.x, totB);
    acc = f2fma(p01, prp01[5], f2mul(p23, prp23[5]));           totA = f2fma(acc, c45.y, totA);
    acc = f2fma(p01, prp01[6], f2mul(p23, prp23[6]));           totB = f2fma(acc, c67.x, totB);
    acc = f2fma(p01, prp01[7], f2mul(p23, prp23[7]));           totA = f2fma(acc, c67.y, totA);
    acc = f2fma(p01, prp01[8], f2mul(p23, prp23[8]));           totB = f2fma(acc, c89.x, totB);
    acc = f2fma(p01, prp01[9], f2mul(p23, prp23[9]));           totA = f2fma(acc, c89.y, totA);
}

// ---------------- kernel 2: persistent main pass over W ----------------
__global__ __launch_bounds__(256, 2)
void prcut_main(const float* __restrict__ W, const float* __restrict__ Pr) {
    const int b  = blockIdx.x;
    const int t0 = (b * NTILE) / NBLK;
    const int t1 = ((b + 1) * NTILE) / NBLK;

    unsigned long long prp01[KK], prp23[KK];
    int cc = -1;
    unsigned long long totA = 0ull, totB = 0ull;
    const float4* W4 = reinterpret_cast<const float4*>(W);

    for (int t = t0; t < t1; t++) {
        const int colChunk = t >> 8;       // 0..7
        const int rowTile  = t & 255;      // 0..255

        if (colChunk != cc) {              // rare: <=1 crossing per block
            cc = colChunk;
            const int col = colChunk * 1024 + threadIdx.x * 4;
#pragma unroll
            for (int k = 0; k < KK; k++) {
                prp01[k] = f2pk(__ldg(&Pr[(size_t)(col + 0) * KK + k]),
                                __ldg(&Pr[(size_t)(col + 1) * KK + k]));
                prp23[k] = f2pk(__ldg(&Pr[(size_t)(col + 2) * KK + k]),
                                __ldg(&Pr[(size_t)(col + 3) * KK + k]));
            }
        }

        const int row0 = rowTile * ROWS_PER_TILE;
        const float4* wp = W4 + (size_t)row0 * (BB / 4) + colChunk * 256 + threadIdx.x;

#pragma unroll 1
        for (int r = 0; r < ROWS_PER_TILE; r += 4) {
            // batch 4 independent row loads for MLP
            float4 w0 = __ldg(wp);
            float4 w1 = __ldg(wp + 1 * (BB / 4));
            float4 w2 = __ldg(wp + 2 * (BB / 4));
            float4 w3 = __ldg(wp + 3 * (BB / 4));
            wp += 4 * (BB / 4);
            const int a = row0 + r;
            row_accum(w0, a + 0, prp01, prp23, totA, totB);
            row_accum(w1, a + 1, prp01, prp23, totA, totB);
            row_accum(w2, a + 2, prp01, prp23, totA, totB);
            row_accum(w3, a + 3, prp01, prp23, totA, totB);
        }
    }

    float tv = f2sum(totA) + f2sum(totB);
#pragma unroll
    for (int off = 16; off > 0; off >>= 1)
        tv += __shfl_xor_sync(0xFFFFFFFFu, tv, off);

    __shared__ float sred[8];
    const int wid = threadIdx.x >> 5;
    const int lid = threadIdx.x & 31;
    if (lid == 0) sred[wid] = tv;
    __syncthreads();
    if (threadIdx.x == 0) {
        float s = 0.0f;
#pragma unroll
        for (int i = 0; i < 8; i++) s += sred[i];
        d_bsum[b] = s;
    }
}

// ---------------- kernel 3: deterministic final reduction ----------------
__global__ void prcut_final(float* __restrict__ out) {
    __shared__ float s[512];
    const int t = threadIdx.x;
    s[t] = (t < NBLK) ? d_bsum[t] : 0.0f;
    __syncthreads();
#pragma unroll
    for (int off = 256; off > 0; off >>= 1) {
        if (t < off) s[t] += s[t + off];
        __syncthreads();
    }
    if (t == 0) out[0] = s[0];
}

extern "C" void kernel_launch(void* const* d_in, const int* in_sizes, int n_in,
                              void* d_out, int out_size) {
    const float* W  = (const float*)d_in[0];
    const float* Pl = (const float*)d_in[1];
    const float* Pr = (const float*)d_in[2];
    const float* cp = (const float*)d_in[3];
    float* out = (float*)d_out;

    prcut_prep<<<AA / 64, 256>>>(Pl, cp);
    prcut_main<<<NBLK, 256>>>(W, Pr);
    prcut_final<<<1, 512>>>(out);
}

// round 9
// speedup vs baseline: 1.4570x; 1.2706x over previous
#include <cuda_runtime.h>

#define AA 8192
#define BB 8192
#define KK 10
#define NBLK 296          // 2 CTAs/SM on 148 SMs (<=2/SM on 152) -> single wave
#define NTILE 2048        // 8 col-chunks x 256 row-tiles
#define ROWS_PER_TILE 32

// Scratch (no allocations allowed).
// d_cs2: per-row fold coefficients as k-PAIRS, 6 u64 (48 B) per row:
//   u64[0]=(c0,c1) u64[1]=(c2,c3) u64[2]=(c4,c5) u64[3]=(c6,c7) u64[4]=(c8,c9) u64[5]=(s,0)
// where c_k = (1-2*P_l[a,k])/cp[k],  s = sum_k P_l[a,k]/cp[k]
__device__ unsigned long long d_cs2[AA * 6];
__device__ float d_bsum[NBLK];

// ---------------- packed f32x2 helpers ----------------
__device__ __forceinline__ unsigned long long f2pk(float lo, float hi) {
    unsigned long long r;
    asm("mov.b64 %0, {%1, %2};" : "=l"(r) : "f"(lo), "f"(hi));
    return r;
}
__device__ __forceinline__ unsigned long long f2fma(unsigned long long a, unsigned long long b,
                                                    unsigned long long c) {
    unsigned long long d;
    asm("fma.rn.f32x2 %0, %1, %2, %3;" : "=l"(d) : "l"(a), "l"(b), "l"(c));
    return d;
}
__device__ __forceinline__ unsigned long long f2mul(unsigned long long a, unsigned long long b) {
    unsigned long long d;
    asm("mul.rn.f32x2 %0, %1, %2;" : "=l"(d) : "l"(a), "l"(b));
    return d;
}
__device__ __forceinline__ float f2sum(unsigned long long a) {
    float lo, hi;
    asm("mov.b64 {%0, %1}, %2;" : "=f"(lo), "=f"(hi) : "l"(a));
    return lo + hi;
}
__device__ __forceinline__ float f2lo(unsigned long long a) {
    float lo, hi;
    asm("mov.b64 {%0, %1}, %2;" : "=f"(lo), "=f"(hi) : "l"(a));
    return lo;
}

// ---------------- kernel 1: fold coefficients, k-pair layout ----------------
__global__ void prcut_prep(const float* __restrict__ Pl, const float* __restrict__ cp) {
    __shared__ float sh[256 * KK];
    const int row0 = blockIdx.x * 256;
    float inv[KK];
#pragma unroll
    for (int k = 0; k < KK; k++) inv[k] = 1.0f / __ldg(&cp[k]);

    // coalesced staged load of 256 rows of P_l
    const float* src = Pl + (size_t)row0 * KK;
#pragma unroll
    for (int i = 0; i < KK; i++) sh[threadIdx.x + i * 256] = __ldg(&src[threadIdx.x + i * 256]);
    __syncthreads();

    const int a = row0 + threadIdx.x;
    float c[KK], s = 0.0f;
#pragma unroll
    for (int k = 0; k < KK; k++) {
        float pl = sh[threadIdx.x * KK + k];
        c[k] = (1.0f - 2.0f * pl) * inv[k];
        s = fmaf(pl, inv[k], s);
    }
    unsigned long long* dst = d_cs2 + (size_t)a * 6;
#pragma unroll
    for (int j = 0; j < 5; j++) dst[j] = f2pk(c[2 * j], c[2 * j + 1]);
    dst[5] = f2pk(s, 0.0f);
}

// ---------------- per-row fold: k-pair math ----------------
__device__ __forceinline__ void row_accum(float4 w, int a,
                                          const unsigned long long (*prkp)[5],
                                          unsigned long long& t0, unsigned long long& t1,
                                          unsigned long long& t2, unsigned long long& t3,
                                          unsigned long long& t4, float& tots) {
    const ulonglong2* cs = reinterpret_cast<const ulonglong2*>(d_cs2 + (size_t)a * 6);
    ulonglong2 L0 = __ldg(cs + 0);
    ulonglong2 L1 = __ldg(cs + 1);
    ulonglong2 L2 = __ldg(cs + 2);

    unsigned long long wd0 = f2pk(w.x, w.x);
    unsigned long long wd1 = f2pk(w.y, w.y);
    unsigned long long wd2 = f2pk(w.z, w.z);
    unsigned long long wd3 = f2pk(w.w, w.w);
    unsigned long long acc;

    acc = f2fma(wd1, prkp[1][0], f2mul(wd0, prkp[0][0]));
    acc = f2fma(wd3, prkp[3][0], f2fma(wd2, prkp[2][0], acc));
    t0 = f2fma(acc, L0.x, t0);

    acc = f2fma(wd1, prkp[1][1], f2mul(wd0, prkp[0][1]));
    acc = f2fma(wd3, prkp[3][1], f2fma(wd2, prkp[2][1], acc));
    t1 = f2fma(acc, L0.y, t1);

    acc = f2fma(wd1, prkp[1][2], f2mul(wd0, prkp[0][2]));
    acc = f2fma(wd3, prkp[3][2], f2fma(wd2, prkp[2][2], acc));
    t2 = f2fma(acc, L1.x, t2);

    acc = f2fma(wd1, prkp[1][3], f2mul(wd0, prkp[0][3]));
    acc = f2fma(wd3, prkp[3][3], f2fma(wd2, prkp[2][3], acc));
    t3 = f2fma(acc, L1.y, t3);

    acc = f2fma(wd1, prkp[1][4], f2mul(wd0, prkp[0][4]));
    acc = f2fma(wd3, prkp[3][4], f2fma(wd2, prkp[2][4], acc));
    t4 = f2fma(acc, L2.x, t4);

    float rs = (w.x + w.y) + (w.z + w.w);
    tots = fmaf(rs, f2lo(L2.y), tots);
}

// ---------------- kernel 2: persistent main pass over W ----------------
__global__ __launch_bounds__(256, 2)
void prcut_main(const float* __restrict__ W, const float* __restrict__ Pr) {
    const int b  = blockIdx.x;
    const int t0r = (b * NTILE) / NBLK;
    const int t1r = ((b + 1) * NTILE) / NBLK;

    // P_r register tile in k-pair form: prkp[c][j] = (P_r[b_c,2j], P_r[b_c,2j+1])
    unsigned long long prkp[4][5];
    int cc = -1;
    unsigned long long t0 = 0ull, t1 = 0ull, t2 = 0ull, t3 = 0ull, t4 = 0ull;
    float tots = 0.0f;
    const float4* W4 = reinterpret_cast<const float4*>(W);

    for (int t = t0r; t < t1r; t++) {
        const int colChunk = t >> 8;       // 0..7
        const int rowTile  = t & 255;      // 0..255

        if (colChunk != cc) {              // rare: <=1 crossing per block
            cc = colChunk;
            const int col = colChunk * 1024 + threadIdx.x * 4;
#pragma unroll
            for (int c = 0; c < 4; c++) {
                const float2* prow = reinterpret_cast<const float2*>(Pr + (size_t)(col + c) * KK);
#pragma unroll
                for (int j = 0; j < 5; j++) {
                    float2 p = __ldg(&prow[j]);
                    prkp[c][j] = f2pk(p.x, p.y);
                }
            }
        }

        const int row0 = rowTile * ROWS_PER_TILE;
        const float4* wp = W4 + (size_t)row0 * (BB / 4) + colChunk * 256 + threadIdx.x;

#pragma unroll 1
        for (int r = 0; r < ROWS_PER_TILE; r += 8) {
            // batch 8 independent W row loads: 4 KB in flight per warp
            float4 w0 = __ldg(wp + 0 * (BB / 4));
            float4 w1 = __ldg(wp + 1 * (BB / 4));
            float4 w2 = __ldg(wp + 2 * (BB / 4));
            float4 w3 = __ldg(wp + 3 * (BB / 4));
            float4 w4 = __ldg(wp + 4 * (BB / 4));
            float4 w5 = __ldg(wp + 5 * (BB / 4));
            float4 w6 = __ldg(wp + 6 * (BB / 4));
            float4 w7 = __ldg(wp + 7 * (BB / 4));
            wp += 8 * (BB / 4);
            const int a = row0 + r;
            row_accum(w0, a + 0, prkp, t0, t1, t2, t3, t4, tots);
            row_accum(w1, a + 1, prkp, t0, t1, t2, t3, t4, tots);
            row_accum(w2, a + 2, prkp, t0, t1, t2, t3, t4, tots);
            row_accum(w3, a + 3, prkp, t0, t1, t2, t3, t4, tots);
            row_accum(w4, a + 4, prkp, t0, t1, t2, t3, t4, tots);
            row_accum(w5, a + 5, prkp, t0, t1, t2, t3, t4, tots);
            row_accum(w6, a + 6, prkp, t0, t1, t2, t3, t4, tots);
            row_accum(w7, a + 7, prkp, t0, t1, t2, t3, t4, tots);
        }
    }

    float tv = tots + f2sum(t0) + f2sum(t1) + f2sum(t2) + f2sum(t3) + f2sum(t4);
#pragma unroll
    for (int off = 16; off > 0; off >>= 1)
        tv += __shfl_xor_sync(0xFFFFFFFFu, tv, off);

    __shared__ float sred[8];
    const int wid = threadIdx.x >> 5;
    const int lid = threadIdx.x & 31;
    if (lid == 0) sred[wid] = tv;
    __syncthreads();
    if (threadIdx.x == 0) {
        float s = 0.0f;
#pragma unroll
        for (int i = 0; i < 8; i++) s += sred[i];
        d_bsum[b] = s;
    }
}

// ---------------- kernel 3: deterministic final reduction ----------------
__global__ void prcut_final(float* __restrict__ out) {
    __shared__ float s[512];
    const int t = threadIdx.x;
    s[t] = (t < NBLK) ? d_bsum[t] : 0.0f;
    __syncthreads();
#pragma unroll
    for (int off = 256; off > 0; off >>= 1) {
        if (t < off) s[t] += s[t + off];
        __syncthreads();
    }
    if (t == 0) out[0] = s[0];
}

extern "C" void kernel_launch(void* const* d_in, const int* in_sizes, int n_in,
                              void* d_out, int out_size) {
    const float* W  = (const float*)d_in[0];
    const float* Pl = (const float*)d_in[1];
    const float* Pr = (const float*)d_in[2];
    const float* cp = (const float*)d_in[3];
    float* out = (float*)d_out;

    prcut_prep<<<AA / 256, 256>>>(Pl, cp);
    prcut_main<<<NBLK, 256>>>(W, Pr);
    prcut_final<<<1, 512>>>(out);
}

// round 11
// speedup vs baseline: 1.9450x; 1.3349x over previous
#include <cuda_runtime.h>

#define AA 8192
#define BB 8192
#define KK 10
#define NBLK 296          // 2 CTAs/SM on 148 SMs (<=2/SM on 152) -> single wave
#define NTILE 2048        // tile = 32 rows x 1024 cols; colChunk = t>>8, rowTile = t&255
#define MAXSLOTS 8        // max tiles per block (ceil(2048/296)+1)

// Scratch (no allocations allowed).
__device__ float d_bsum[NBLK];
__device__ unsigned int d_count = 0;

// ---------------- packed f32x2 helpers ----------------
__device__ __forceinline__ unsigned long long f2pk(float lo, float hi) {
    unsigned long long r;
    asm("mov.b64 %0, {%1, %2};" : "=l"(r) : "f"(lo), "f"(hi));
    return r;
}
__device__ __forceinline__ unsigned long long f2fma(unsigned long long a, unsigned long long b,
                                                    unsigned long long c) {
    unsigned long long d;
    asm("fma.rn.f32x2 %0, %1, %2, %3;" : "=l"(d) : "l"(a), "l"(b), "l"(c));
    return d;
}
__device__ __forceinline__ unsigned long long f2mul(unsigned long long a, unsigned long long b) {
    unsigned long long d;
    asm("mul.rn.f32x2 %0, %1, %2;" : "=l"(d) : "l"(a), "l"(b));
    return d;
}
__device__ __forceinline__ float f2sum(unsigned long long a) {
    float lo, hi;
    asm("mov.b64 {%0, %1}, %2;" : "=f"(lo), "=f"(hi) : "l"(a));
    return lo + hi;
}
__device__ __forceinline__ float f2lo(unsigned long long a) {
    float lo, hi;
    asm("mov.b64 {%0, %1}, %2;" : "=f"(lo), "=f"(hi) : "l"(a));
    return lo;
}

// ---------------- per-row fold: k-pair math, coefficients from SMEM ----------------
__device__ __forceinline__ void row_accum(float4 w, const ulonglong2* __restrict__ cs,
                                          const unsigned long long (*prkp)[5],
                                          unsigned long long& t0, unsigned long long& t1,
                                          unsigned long long& t2, unsigned long long& t3,
                                          unsigned long long& t4, float& tots) {
    ulonglong2 L0 = cs[0];   // (c0,c1)(c2,c3)
    ulonglong2 L1 = cs[1];   // (c4,c5)(c6,c7)
    ulonglong2 L2 = cs[2];   // (c8,c9)(s, 0)

    unsigned long long wd0 = f2pk(w.x, w.x);
    unsigned long long wd1 = f2pk(w.y, w.y);
    unsigned long long wd2 = f2pk(w.z, w.z);
    unsigned long long wd3 = f2pk(w.w, w.w);
    unsigned long long acc;

    acc = f2fma(wd1, prkp[1][0], f2mul(wd0, prkp[0][0]));
    acc = f2fma(wd3, prkp[3][0], f2fma(wd2, prkp[2][0], acc));
    t0 = f2fma(acc, L0.x, t0);

    acc = f2fma(wd1, prkp[1][1], f2mul(wd0, prkp[0][1]));
    acc = f2fma(wd3, prkp[3][1], f2fma(wd2, prkp[2][1], acc));
    t1 = f2fma(acc, L0.y, t1);

    acc = f2fma(wd1, prkp[1][2], f2mul(wd0, prkp[0][2]));
    acc = f2fma(wd3, prkp[3][2], f2fma(wd2, prkp[2][2], acc));
    t2 = f2fma(acc, L1.x, t2);

    acc = f2fma(wd1, prkp[1][3], f2mul(wd0, prkp[0][3]));
    acc = f2fma(wd3, prkp[3][3], f2fma(wd2, prkp[2][3], acc));
    t3 = f2fma(acc, L1.y, t3);

    acc = f2fma(wd1, prkp[1][4], f2mul(wd0, prkp[0][4]));
    acc = f2fma(wd3, prkp[3][4], f2fma(wd2, prkp[2][4], acc));
    t4 = f2fma(acc, L2.x, t4);

    float rs = (w.x + w.y) + (w.z + w.w);
    tots = fmaf(rs, f2lo(L2.y), tots);
}

// ---------------- single fused kernel ----------------
__global__ __launch_bounds__(256, 2)
void prcut_fused(const float* __restrict__ W, const float* __restrict__ Pl,
                 const float* __restrict__ Pr, const float* __restrict__ cp,
                 float* __restrict__ out) {
    // cs_sm[slot][row][6] u64 pairs: (c0,c1)..(c8,c9),(s,0). 48B/row, 16B aligned.
    __shared__ unsigned long long cs_sm[MAXSLOTS * 32 * 6];   // 12 KB
    __shared__ float sred[8];
    __shared__ int is_last;

    const int b   = blockIdx.x;
    const int tB0 = (b * NTILE) / NBLK;
    const int tB1 = ((b + 1) * NTILE) / NBLK;
    const int nslots = tB1 - tB0;

    // ---- stage fold coefficients for this block's tiles (one row per thread) ----
    {
        const int slot = threadIdx.x >> 5;
        const int row  = threadIdx.x & 31;
        if (slot < nslots) {
            const int rowTile = (tB0 + slot) & 255;
            const int a = rowTile * 32 + row;
            float inv[KK];
#pragma unroll
            for (int k = 0; k < KK; k++) inv[k] = 1.0f / __ldg(&cp[k]);
            const float2* plrow = reinterpret_cast<const float2*>(Pl + (size_t)a * KK);
            unsigned long long* dst = &cs_sm[(slot * 32 + row) * 6];
            float s = 0.0f;
#pragma unroll
            for (int j = 0; j < 5; j++) {
                float2 p = __ldg(&plrow[j]);
                float c0 = (1.0f - 2.0f * p.x) * inv[2 * j];
                float c1 = (1.0f - 2.0f * p.y) * inv[2 * j + 1];
                dst[j] = f2pk(c0, c1);
                s = fmaf(p.x, inv[2 * j], s);
                s = fmaf(p.y, inv[2 * j + 1], s);
            }
            dst[5] = f2pk(s, 0.0f);
        }
    }
    __syncthreads();

    // ---- main pass over W ----
    unsigned long long prkp[4][5];   // prkp[c][j] = (P_r[b_c,2j], P_r[b_c,2j+1])
    int cc = -1;
    unsigned long long t0 = 0ull, t1 = 0ull, t2 = 0ull, t3 = 0ull, t4 = 0ull;
    float tots = 0.0f;
    const float4* W4 = reinterpret_cast<const float4*>(W);

    for (int t = tB0; t < tB1; t++) {
        const int colChunk = t >> 8;
        const int rowTile  = t & 255;
        const int slot     = t - tB0;

        if (colChunk != cc) {              // <=1 crossing per block
            cc = colChunk;
            const int col = colChunk * 1024 + threadIdx.x * 4;
#pragma unroll
            for (int c = 0; c < 4; c++) {
                const float2* prow = reinterpret_cast<const float2*>(Pr + (size_t)(col + c) * KK);
#pragma unroll
                for (int j = 0; j < 5; j++) {
                    float2 p = __ldg(&prow[j]);
                    prkp[c][j] = f2pk(p.x, p.y);
                }
            }
        }

        const float4* wp = W4 + (size_t)(rowTile * 32) * (BB / 4) + colChunk * 256 + threadIdx.x;
        const ulonglong2* csbase = reinterpret_cast<const ulonglong2*>(&cs_sm[slot * 32 * 6]);

#pragma unroll 1
        for (int r = 0; r < 32; r += 8) {
            // batch 8 independent W row loads: 4 KB in flight per warp
            float4 w0 = __ldg(wp + 0 * (BB / 4));
            float4 w1 = __ldg(wp + 1 * (BB / 4));
            float4 w2 = __ldg(wp + 2 * (BB / 4));
            float4 w3 = __ldg(wp + 3 * (BB / 4));
            float4 w4 = __ldg(wp + 4 * (BB / 4));
            float4 w5 = __ldg(wp + 5 * (BB / 4));
            float4 w6 = __ldg(wp + 6 * (BB / 4));
            float4 w7 = __ldg(wp + 7 * (BB / 4));
            wp += 8 * (BB / 4);
            const ulonglong2* csr = csbase + r * 3;
            row_accum(w0, csr + 0 * 3, prkp, t0, t1, t2, t3, t4, tots);
            row_accum(w1, csr + 1 * 3, prkp, t0, t1, t2, t3, t4, tots);
            row_accum(w2, csr + 2 * 3, prkp, t0, t1, t2, t3, t4, tots);
            row_accum(w3, csr + 3 * 3, prkp, t0, t1, t2, t3, t4, tots);
            row_accum(w4, csr + 4 * 3, prkp, t0, t1, t2, t3, t4, tots);
            row_accum(w5, csr + 5 * 3, prkp, t0, t1, t2, t3, t4, tots);
            row_accum(w6, csr + 6 * 3, prkp, t0, t1, t2, t3, t4, tots);
            row_accum(w7, csr + 7 * 3, prkp, t0, t1, t2, t3, t4, tots);
        }
    }

    // ---- block reduction ----
    float tv = tots + f2sum(t0) + f2sum(t1) + f2sum(t2) + f2sum(t3) + f2sum(t4);
#pragma unroll
    for (int off = 16; off > 0; off >>= 1)
        tv += __shfl_xor_sync(0xFFFFFFFFu, tv, off);

    const int wid = threadIdx.x >> 5;
    const int lid = threadIdx.x & 31;
    if (lid == 0) sred[wid] = tv;
    __syncthreads();
    if (threadIdx.x == 0) {
        float s = 0.0f;
#pragma unroll
        for (int i = 0; i < 8; i++) s += sred[i];
        d_bsum[b] = s;
        __threadfence();
        unsigned int old = atomicAdd(&d_count, 1u);
        is_last = (old == NBLK - 1) ? 1 : 0;
    }
    __syncthreads();

    // ---- last block: deterministic final reduction + counter reset for graph replay ----
    if (is_last) {
        __threadfence();
        __shared__ float fin[256];
        const int tdx = threadIdx.x;
        float v = 0.0f;
        if (tdx < NBLK) v = *((volatile float*)&d_bsum[tdx]);
        if (tdx + 256 < NBLK) v += *((volatile float*)&d_bsum[tdx + 256]);
        fin[tdx] = v;
        __syncthreads();
#pragma unroll
        for (int off = 128; off > 0; off >>= 1) {
            if (tdx < off) fin[tdx] += fin[tdx + off];
            __syncthreads();
        }
        if (tdx == 0) {
            d_count = 0;   // reset for next graph replay (only last block writes)
            out[0] = fin[0];
        }
    }
}

extern "C" void kernel_launch(void* const* d_in, const int* in_sizes, int n_in,
                              void* d_out, int out_size) {
    const float* W  = (const float*)d_in[0];
    const float* Pl = (const float*)d_in[1];
    const float* Pr = (const float*)d_in[2];
    const float* cp = (const float*)d_in[3];
    float* out = (float*)d_out;

    prcut_fused<<<NBLK, 256>>>(W, Pl, Pr, cp, out);
}